// round 16
// baseline (speedup 1.0000x reference)
#include <cuda_runtime.h>
#include <cstdint>

// KDPointToPointLoss: loss[b] = (1/(3N)) * sum_n min_m ||s[b,:,n] - t[b,:,m]||^2
// B=8, C=3, N=M=4096 (fixed by dataset).
//
// Dense exact fp32. score(n,m) = |t_m|^2 - 2 s_n.t_m (monotone in d2).
// Main-loop fp32 FMA-pipe floor ~22.3us (402M lane-FMAs). Targets in smem as
// two interleaved 16B words per pair -> 2x LDS.128 per j2; fma.rn.f32x2 x3 +
// 2 scalar FMNMX per (pair, point). ILP=8 source points/thread + TSPLIT=64
// (TC2=32) fully unrolled: 2.625 issue slots/pair, body ~21KB (fits L1.5 I$).
//
// Combine: enc(d2) = ~bits(d2); for d2 >= 0 min-d2 == max-enc, identity 0.
// No-return atomicMax (REDG); zero-init IS the identity; finishers reset to 0.
// Two-level fused reduction pipelined into the wave:
//  L1: last block of each (batch, src-chunk) 64-block group sums its 1024 pts.
//  L2: last L1 finisher per batch sums 4 chunk sums in fixed order -> out[b].
// All counters self-reset -> graph-replay safe; orders fixed -> deterministic.

#define BATCH 8
#define NPTS  4096
#define MPTS  4096

#define THREADS   128
#define ILP       8                       // source points per thread
#define SRC_PER_BLOCK (THREADS * ILP)     // 1024
#define SRC_CHUNKS (NPTS / SRC_PER_BLOCK) // 4
#define TSPLIT    64                      // target splits
#define TC        (MPTS / TSPLIT)         // 64 targets per block
#define TC2       (TC / 2)                // 32 packed pairs

__device__ unsigned int g_enc[BATCH * NPTS];          // ~bits(min d2); 0 = identity
__device__ float        g_csum[BATCH * SRC_CHUNKS];   // per-chunk sums
__device__ int          g_cnt1[BATCH * SRC_CHUNKS];   // L1 counters (to TSPLIT)
__device__ int          g_cnt2[BATCH];                // L2 counters (to SRC_CHUNKS)

__device__ __forceinline__ unsigned long long ffma2(
    unsigned long long a, unsigned long long b, unsigned long long c) {
    unsigned long long d;
    asm("fma.rn.f32x2 %0, %1, %2, %3;" : "=l"(d) : "l"(a), "l"(b), "l"(c));
    return d;
}
__device__ __forceinline__ unsigned long long pack2(float lo, float hi) {
    unsigned long long r;
    asm("mov.b64 %0, {%1, %2};" : "=l"(r) : "f"(lo), "f"(hi));
    return r;
}
__device__ __forceinline__ void unpack2(unsigned long long v, float& lo, float& hi) {
    asm("mov.b64 {%0, %1}, %2;" : "=f"(lo), "=f"(hi) : "l"(v));
}

__global__ __launch_bounds__(THREADS) void nn_kernel(
    const float* __restrict__ src, const float* __restrict__ tgt,
    float* __restrict__ out) {
    // Interleaved: sxy[j2] = {packed x pair, packed y pair},
    //              szw[j2] = {packed z pair, packed |t|^2 pair} -> LDS.128.
    __shared__ ulonglong2 sxy[TC2], szw[TC2];
    __shared__ float shred[THREADS];
    __shared__ int amLast1, amLast2;

    const int ts   = blockIdx.x;               // target split
    const int sc   = blockIdx.y;               // source chunk
    const int src0 = sc * SRC_PER_BLOCK;
    const int b    = blockIdx.z;
    const int tid  = threadIdx.x;
    const int tgt0 = ts * TC;

    // Cooperative packed load of this target chunk (TC2 = 32 < THREADS).
    const float2* tx = (const float2*)(tgt + (size_t)b * 3 * MPTS + 0 * MPTS + tgt0);
    const float2* ty = (const float2*)(tgt + (size_t)b * 3 * MPTS + 1 * MPTS + tgt0);
    const float2* tz = (const float2*)(tgt + (size_t)b * 3 * MPTS + 2 * MPTS + tgt0);
    if (tid < TC2) {
        int j2 = tid;
        float2 x = tx[j2];
        float2 y = ty[j2];
        float2 z = tz[j2];
        float w0 = fmaf(x.x, x.x, fmaf(y.x, y.x, z.x * z.x));
        float w1 = fmaf(x.y, x.y, fmaf(y.y, y.y, z.y * z.y));
        sxy[j2] = make_ulonglong2(pack2(x.x, x.y), pack2(y.x, y.y));
        szw[j2] = make_ulonglong2(pack2(z.x, z.y), pack2(w0, w1));
    }

    // Per-thread source points: packed duplicated coefficients (-2s, -2s).
    const float* sb = src + (size_t)b * 3 * NPTS;
    unsigned long long cx2[ILP], cy2[ILP], cz2[ILP];
    float s2[ILP], mnLo[ILP], mnHi[ILP];
#pragma unroll
    for (int p = 0; p < ILP; p++) {
        int n = src0 + p * THREADS + tid;
        float sx = sb[0 * NPTS + n];
        float sy = sb[1 * NPTS + n];
        float sz = sb[2 * NPTS + n];
        cx2[p] = pack2(-2.0f * sx, -2.0f * sx);
        cy2[p] = pack2(-2.0f * sy, -2.0f * sy);
        cz2[p] = pack2(-2.0f * sz, -2.0f * sz);
        s2[p]  = fmaf(sx, sx, fmaf(sy, sy, sz * sz));
        mnLo[p] = 1e30f;
        mnHi[p] = 1e30f;
    }
    __syncthreads();

    // Main loop, FULLY UNROLLED (TC2=32): per j2 (2 targets):
    // 2 LDS.128 + ILP*(3 FFMA2 + 2 FMNMX) -> 2.625 issue slots per pair.
#pragma unroll
    for (int j2 = 0; j2 < TC2; j2++) {
        ulonglong2 vxy = sxy[j2];
        ulonglong2 vzw = szw[j2];
#pragma unroll
        for (int p = 0; p < ILP; p++) {
            unsigned long long acc = ffma2(cz2[p], vzw.x, vzw.y);
            acc = ffma2(cy2[p], vxy.y, acc);
            acc = ffma2(cx2[p], vxy.x, acc);
            float lo, hi;
            unpack2(acc, lo, hi);
            mnLo[p] = fminf(mnLo[p], lo);
            mnHi[p] = fminf(mnHi[p], hi);
        }
    }

    // Combine across target splits: min-d2 == max-enc, identity 0 (REDG).
#pragma unroll
    for (int p = 0; p < ILP; p++) {
        int n = src0 + p * THREADS + tid;
        float d2 = fmaxf(fminf(mnLo[p], mnHi[p]) + s2[p], 0.0f);
        atomicMax(&g_enc[b * NPTS + n], ~__float_as_uint(d2));
    }

    // ---- L1: last block of this (batch, src-chunk) 64-block group ----
    if (tid == 0) {
        __threadfence();                       // publish REDG results
        int prev = atomicAdd(&g_cnt1[b * SRC_CHUNKS + sc], 1);
        amLast1 = (prev == TSPLIT - 1);
        if (amLast1) g_cnt1[b * SRC_CHUNKS + sc] = 0;  // reset for replay
    }
    __syncthreads();
    if (amLast1) {
        __threadfence();                       // acquire peers' REDG writes
        // 1024 points: two uint4 per thread; read, reset, decode, sum.
        uint4* pe = (uint4*)(g_enc + (size_t)b * NPTS + src0);
        float s = 0.0f;
#pragma unroll
        for (int k = 0; k < SRC_PER_BLOCK / 4 / THREADS; k++) {   // 2 iters
            int i = k * THREADS + tid;
            uint4 v = pe[i];
            pe[i] = make_uint4(0u, 0u, 0u, 0u);  // reset identity for replay
            s += __uint_as_float(~v.x) + __uint_as_float(~v.y) +
                 __uint_as_float(~v.z) + __uint_as_float(~v.w);
        }
        shred[tid] = s;
        __syncthreads();
        for (int o = THREADS / 2; o > 0; o >>= 1) {
            if (tid < o) shred[tid] += shred[tid + o];
            __syncthreads();
        }
        // ---- L2: last chunk-finisher of this batch sums 4 chunk sums ----
        if (tid == 0) {
            g_csum[b * SRC_CHUNKS + sc] = shred[0];
            __threadfence();
            int prev = atomicAdd(&g_cnt2[b], 1);
            amLast2 = (prev == SRC_CHUNKS - 1);
            if (amLast2) g_cnt2[b] = 0;        // reset for replay
        }
        __syncthreads();
        if (amLast2 && tid == 0) {
            __threadfence();
            float tot = 0.0f;
#pragma unroll
            for (int t = 0; t < SRC_CHUNKS; t++) tot += g_csum[b * SRC_CHUNKS + t];
            out[b] = tot * (1.0f / (3.0f * NPTS));
        }
    }
}

extern "C" void kernel_launch(void* const* d_in, const int* in_sizes, int n_in,
                              void* d_out, int out_size) {
    const float* src = (const float*)d_in[0];  // [B,3,N]
    const float* tgt = (const float*)d_in[1];  // [B,3,M]
    float* out = (float*)d_out;                // [B]

    dim3 grid(TSPLIT, SRC_CHUNKS, BATCH);      // 64 x 4 x 8 = 2048 blocks
    nn_kernel<<<grid, THREADS>>>(src, tgt, out);
}